// round 1
// baseline (speedup 1.0000x reference)
#include <cuda_runtime.h>

#define BB 32
#define PP 32768
#define OO 32
#define CBLK 256
#define NBLK (PP / CBLK)  // 128 blocks per batch

// ---------------- scratch (no allocations allowed) ----------------
__device__ unsigned long long g_bp_key[BB * OO];   // per (b,o): packed (iou, ~p)
__device__ float g_bto[BB * PP];                   // best_truth_overlap
__device__ int   g_bti[BB * PP];                   // best_truth_idx
__device__ float g_ce[BB * PP];                    // ce_mine
__device__ float g_pl[BB * NBLK];                  // partial loss_l
__device__ float g_pc[BB * NBLK];                  // partial sum_pos ce
__device__ int   g_pn[BB * NBLK];                  // partial num_pos
__device__ float g_bl[BB], g_bc[BB], g_bt[BB];     // per-batch loss_l, pos-ce, topk
__device__ int   g_bn[BB];                         // per-batch num_pos

// ---------------- init: reset the argmax keys ----------------
__global__ void k_init() {
    int i = threadIdx.x;
    // key for iou=0, p=0 (matches jnp.argmax of an all-zero row -> index 0)
    if (i < BB * OO) g_bp_key[i] = 0x00000000FFFFFFFFull;
}

// ---------------- match: IoU + both argmaxes ----------------
__global__ __launch_bounds__(CBLK) void k_match(const float4* __restrict__ priors,
                                                const float*  __restrict__ targets) {
    __shared__ float tx1[OO], ty1[OO], tx2[OO], ty2[OO], tar[OO];
    __shared__ unsigned long long sbest[OO];
    const int b = blockIdx.y;
    const int tid = threadIdx.x;
    if (tid < OO) {
        const float* t = targets + (size_t)(b * OO + tid) * 5;
        float x1 = t[0], y1 = t[1], x2 = t[2], y2 = t[3];
        tx1[tid] = x1; ty1[tid] = y1; tx2[tid] = x2; ty2[tid] = y2;
        tar[tid] = (x2 - x1) * (y2 - y1);
        sbest[tid] = 0ull;
    }
    __syncthreads();

    const int p = blockIdx.x * CBLK + tid;
    float4 pr = priors[p];
    float px1 = pr.x - pr.z * 0.5f, py1 = pr.y - pr.w * 0.5f;
    float px2 = pr.x + pr.z * 0.5f, py2 = pr.y + pr.w * 0.5f;
    float areab = (px2 - px1) * (py2 - py1);  // matches ref: area from point_form

    float bestv = -1.0f; int besti = 0;
    #pragma unroll
    for (int o = 0; o < OO; o++) {
        float ix1 = fmaxf(tx1[o], px1), iy1 = fmaxf(ty1[o], py1);
        float ix2 = fminf(tx2[o], px2), iy2 = fminf(ty2[o], py2);
        float w = fmaxf(ix2 - ix1, 0.0f), h = fmaxf(iy2 - iy1, 0.0f);
        float inter = w * h;
        float iou = inter / (tar[o] + areab - inter);
        if (iou > bestv) { bestv = iou; besti = o; }  // strict > -> first-max, like jnp.argmax
        if (inter > 0.0f) {
            // higher iou wins; among equal iou, smaller p wins (first-index tie-break)
            unsigned long long key =
                ((unsigned long long)__float_as_uint(iou) << 32) |
                (unsigned)(0xFFFFFFFFu - (unsigned)p);
            atomicMax(&sbest[o], key);
        }
    }
    g_bto[(size_t)b * PP + p] = bestv;
    g_bti[(size_t)b * PP + p] = besti;
    __syncthreads();
    if (tid < OO && sbest[tid])
        atomicMax(&g_bp_key[b * OO + tid], sbest[tid]);
}

// ---------------- scatter override (last-o-wins, serial per batch) ----------------
__global__ void k_override() {
    int b = threadIdx.x;
    if (b < BB) {
        for (int o = 0; o < OO; o++) {
            unsigned p = 0xFFFFFFFFu - (unsigned)(g_bp_key[b * OO + o] & 0xFFFFFFFFull);
            g_bto[(size_t)b * PP + p] = 2.0f;
            g_bti[(size_t)b * PP + p] = o;
        }
    }
}

// ---------------- per-prior loss terms ----------------
__global__ __launch_bounds__(CBLK) void k_loss(const float*  __restrict__ loc,
                                               const float2* __restrict__ conf,
                                               const float4* __restrict__ priors,
                                               const float*  __restrict__ targets) {
    __shared__ float tx1[OO], ty1[OO], tx2[OO], ty2[OO], tlb[OO];
    __shared__ float s_l[CBLK], s_c[CBLK];
    __shared__ int   s_n[CBLK];
    const int b = blockIdx.y, tid = threadIdx.x;
    if (tid < OO) {
        const float* t = targets + (size_t)(b * OO + tid) * 5;
        tx1[tid] = t[0]; ty1[tid] = t[1]; tx2[tid] = t[2]; ty2[tid] = t[3]; tlb[tid] = t[4];
    }
    __syncthreads();

    const int p = blockIdx.x * CBLK + tid;
    const size_t bp = (size_t)b * PP + p;
    float ov = g_bto[bp];
    int idx = g_bti[bp];
    int cls = (ov < 0.5f) ? 0 : (int)tlb[idx];
    bool pos = cls > 0;

    float4 pr = priors[p];
    float gx = ((tx1[idx] + tx2[idx]) * 0.5f - pr.x) / (0.1f * pr.z);
    float gy = ((ty1[idx] + ty2[idx]) * 0.5f - pr.y) / (0.1f * pr.w);
    float gw = logf((tx2[idx] - tx1[idx]) / pr.z) / 0.2f;
    float gh = logf((ty2[idx] - ty1[idx]) / pr.w) / 0.2f;

    const float* l = loc + bp * 3;
    float q0 = l[0], q1 = l[1], q2 = l[2];
    float d0 = q0 - gx, d1 = q1 - gy, d2 = q2 - gw, d3 = q2 - gh;

    float ad, lloss = 0.0f;
    ad = fabsf(d0); lloss += (ad < 1.0f) ? 0.5f * d0 * d0 : ad - 0.5f;
    ad = fabsf(d1); lloss += (ad < 1.0f) ? 0.5f * d1 * d1 : ad - 0.5f;
    ad = fabsf(d2); lloss += (ad < 1.0f) ? 0.5f * d2 * d2 : ad - 0.5f;
    ad = fabsf(d3); lloss += (ad < 1.0f) ? 0.5f * d3 * d3 : ad - 0.5f;

    float2 c = conf[bp];
    float m = fmaxf(c.x, c.y);
    float lse = m + logf(expf(c.x - m) + expf(c.y - m));
    float picked = cls ? c.y : c.x;
    float ce = lse - picked;

    s_l[tid] = pos ? lloss : 0.0f;
    s_c[tid] = pos ? ce : 0.0f;
    s_n[tid] = pos ? 1 : 0;
    g_ce[bp] = pos ? 0.0f : fmaxf(ce, 0.0f);
    __syncthreads();
    #pragma unroll
    for (int s = CBLK / 2; s > 0; s >>= 1) {
        if (tid < s) { s_l[tid] += s_l[tid + s]; s_c[tid] += s_c[tid + s]; s_n[tid] += s_n[tid + s]; }
        __syncthreads();
    }
    if (tid == 0) {
        int pb = b * NBLK + blockIdx.x;
        g_pl[pb] = s_l[0]; g_pc[pb] = s_c[0]; g_pn[pb] = s_n[0];
    }
}

// ---------------- radix-select top-k sum (one block per batch) ----------------
__global__ __launch_bounds__(1024) void k_select() {
    __shared__ unsigned hist[2048];
    __shared__ float sred[1024];
    __shared__ unsigned s_prefix;
    __shared__ int s_kr, s_k;
    const int b = blockIdx.x, tid = threadIdx.x;

    if (tid == 0) {
        float sl = 0.f, sc = 0.f; int sn = 0;
        for (int i = 0; i < NBLK; i++) {
            int pb = b * NBLK + i;
            sl += g_pl[pb]; sc += g_pc[pb]; sn += g_pn[pb];
        }
        g_bl[b] = sl; g_bc[b] = sc; g_bn[b] = sn;
        int k = 3 * sn; if (k > PP - 1) k = PP - 1;
        s_k = k; s_kr = k; s_prefix = 0u;
    }
    unsigned v[32];
    #pragma unroll
    for (int i = 0; i < 32; i++)
        v[i] = __float_as_uint(g_ce[(size_t)b * PP + tid + i * 1024]);
    __syncthreads();

    if (s_k == 0) { if (tid == 0) g_bt[b] = 0.0f; return; }

    // pass 1: bits [31:21]
    hist[tid] = 0; hist[tid + 1024] = 0; __syncthreads();
    #pragma unroll
    for (int i = 0; i < 32; i++) atomicAdd(&hist[v[i] >> 21], 1u);
    __syncthreads();
    if (tid == 0) {
        int kr = s_kr; unsigned cum = 0; int sel = 0;
        for (int i = 2047; i >= 0; i--) {
            unsigned c = hist[i];
            if (cum + c >= (unsigned)kr) { sel = i; break; }
            cum += c;
        }
        s_kr = kr - (int)cum; s_prefix = (unsigned)sel << 21;
    }
    __syncthreads();
    unsigned pref = s_prefix;

    // pass 2: bits [20:10]
    hist[tid] = 0; hist[tid + 1024] = 0; __syncthreads();
    #pragma unroll
    for (int i = 0; i < 32; i++)
        if ((v[i] & 0xFFE00000u) == pref) atomicAdd(&hist[(v[i] >> 10) & 0x7FFu], 1u);
    __syncthreads();
    if (tid == 0) {
        int kr = s_kr; unsigned cum = 0; int sel = 0;
        for (int i = 2047; i >= 0; i--) {
            unsigned c = hist[i];
            if (cum + c >= (unsigned)kr) { sel = i; break; }
            cum += c;
        }
        s_kr = kr - (int)cum; s_prefix = pref | ((unsigned)sel << 10);
    }
    __syncthreads();
    pref = s_prefix;

    // pass 3: bits [9:0]
    hist[tid] = 0; __syncthreads();
    #pragma unroll
    for (int i = 0; i < 32; i++)
        if ((v[i] & 0xFFFFFC00u) == pref) atomicAdd(&hist[v[i] & 0x3FFu], 1u);
    __syncthreads();
    if (tid == 0) {
        int kr = s_kr; unsigned cum = 0; int sel = 0;
        for (int i = 1023; i >= 0; i--) {
            unsigned c = hist[i];
            if (cum + c >= (unsigned)kr) { sel = i; break; }
            cum += c;
        }
        s_kr = kr - (int)cum; s_prefix = pref | (unsigned)sel;
    }
    __syncthreads();
    const unsigned tbits = s_prefix;
    const int kr = s_kr;

    float acc = 0.0f;
    #pragma unroll
    for (int i = 0; i < 32; i++)
        if (v[i] > tbits) acc += __uint_as_float(v[i]);
    sred[tid] = acc;
    __syncthreads();
    #pragma unroll
    for (int s = 512; s > 0; s >>= 1) {
        if (tid < s) sred[tid] += sred[tid + s];
        __syncthreads();
    }
    if (tid == 0) g_bt[b] = sred[0] + (float)kr * __uint_as_float(tbits);
}

// ---------------- final combine ----------------
__global__ void k_final(float* out) {
    float sl = 0.f, sc = 0.f; int sn = 0;
    for (int b = 0; b < BB; b++) {
        sl += g_bl[b];
        sc += g_bc[b] + g_bt[b];
        sn += g_bn[b];
    }
    float N = (float)sn;
    out[0] = sl / N;
    out[1] = sc / N;
}

extern "C" void kernel_launch(void* const* d_in, const int* in_sizes, int n_in,
                              void* d_out, int out_size) {
    const float*  loc     = (const float*)d_in[0];   // (B, P, 3)
    const float2* conf    = (const float2*)d_in[1];  // (B, P, 2)
    const float4* priors  = (const float4*)d_in[2];  // (P, 4)
    const float*  targets = (const float*)d_in[3];   // (B, O, 5)
    float* out = (float*)d_out;

    k_init<<<1, 1024>>>();
    k_match<<<dim3(NBLK, BB), CBLK>>>(priors, targets);
    k_override<<<1, 32>>>();
    k_loss<<<dim3(NBLK, BB), CBLK>>>(loc, conf, priors, targets);
    k_select<<<BB, 1024>>>();
    k_final<<<1, 1>>>(out);
}

// round 2
// speedup vs baseline: 1.8813x; 1.8813x over previous
#include <cuda_runtime.h>

#define BB 32
#define PP 32768
#define OO 32
#define CBLK 256
#define NBLK (PP / CBLK)  // 128 blocks per batch

// ---------------- scratch (no allocations allowed) ----------------
__device__ unsigned long long g_bp_key[BB * OO];   // per (b,o): packed (iou, ~p)
__device__ float g_bto[BB * PP];                   // best_truth_overlap
__device__ int   g_bti[BB * PP];                   // best_truth_idx
__device__ float g_ce[BB * PP];                    // ce_mine
__device__ float g_pl[BB * NBLK];                  // partial loss_l
__device__ float g_pc[BB * NBLK];                  // partial sum_pos ce
__device__ int   g_pn[BB * NBLK];                  // partial num_pos
__device__ float g_bl[BB], g_bc[BB], g_bt[BB];     // per-batch loss_l, pos-ce, topk
__device__ int   g_bn[BB];                         // per-batch num_pos
__device__ int   g_done;                           // finalize counter

// ---------------- init: reset keys + counter ----------------
__global__ void k_init() {
    int i = threadIdx.x;
    // key for iou=0, p=0 (matches jnp.argmax of an all-zero row -> index 0)
    if (i < BB * OO) g_bp_key[i] = 0x00000000FFFFFFFFull;
    if (i == 0) g_done = 0;
}

// ---------------- match: transposed warp form ----------------
// lane = truth index; loop i = prior within the warp's 32 priors.
__global__ __launch_bounds__(CBLK) void k_match(const float4* __restrict__ priors,
                                                const float*  __restrict__ targets) {
    __shared__ float tx1[OO], ty1[OO], tx2[OO], ty2[OO], tar[OO];
    __shared__ unsigned long long sbest[OO];
    const int b = blockIdx.y;
    const int tid = threadIdx.x;
    const int lane = tid & 31;
    const int w = tid >> 5;
    if (tid < OO) {
        const float* t = targets + (size_t)(b * OO + tid) * 5;
        float x1 = t[0], y1 = t[1], x2 = t[2], y2 = t[3];
        tx1[tid] = x1; ty1[tid] = y1; tx2[tid] = x2; ty2[tid] = y2;
        tar[tid] = (x2 - x1) * (y2 - y1);
        sbest[tid] = 0ull;
    }
    __syncthreads();

    // this lane's truth (register-resident)
    const float Tx1 = tx1[lane], Ty1 = ty1[lane], Tx2 = tx2[lane], Ty2 = ty2[lane];
    const float Tar = tar[lane];

    // this lane's prior (to be broadcast)
    const int pbase = blockIdx.x * CBLK + w * 32;
    float4 pr = priors[pbase + lane];
    float px1 = pr.x - pr.z * 0.5f, py1 = pr.y - pr.w * 0.5f;
    float px2 = pr.x + pr.z * 0.5f, py2 = pr.y + pr.w * 0.5f;
    float parea = (px2 - px1) * (py2 - py1);

    unsigned long long rkey = 0ull;   // per-truth running (iou, ~p) max
    float my_bto = 0.0f; int my_bti = 0;

    #pragma unroll
    for (int i = 0; i < 32; i++) {
        float bx1 = __shfl_sync(0xffffffffu, px1, i);
        float by1 = __shfl_sync(0xffffffffu, py1, i);
        float bx2 = __shfl_sync(0xffffffffu, px2, i);
        float by2 = __shfl_sync(0xffffffffu, py2, i);
        float ba  = __shfl_sync(0xffffffffu, parea, i);
        float ww = fmaxf(fminf(Tx2, bx2) - fmaxf(Tx1, bx1), 0.0f);
        float hh = fmaxf(fminf(Ty2, by2) - fmaxf(Ty1, by1), 0.0f);
        float inter = ww * hh;
        float iou = inter / (Tar + ba - inter);
        unsigned u = __float_as_uint(iou);   // nonneg float: bits monotonic
        unsigned m = __reduce_max_sync(0xffffffffu, u);
        unsigned bal = __ballot_sync(0xffffffffu, u == m);
        if (lane == i) { my_bto = __uint_as_float(m); my_bti = __ffs(bal) - 1; }
        if (inter > 0.0f) {
            unsigned long long key = ((unsigned long long)u << 32) |
                                     (unsigned)(0xFFFFFFFFu - (unsigned)(pbase + i));
            if (key > rkey) rkey = key;
        }
    }
    const size_t bp = (size_t)b * PP + pbase + lane;
    g_bto[bp] = my_bto;
    g_bti[bp] = my_bti;
    if (rkey) atomicMax(&sbest[lane], rkey);
    __syncthreads();
    if (tid < OO && sbest[tid])
        atomicMax(&g_bp_key[b * OO + tid], sbest[tid]);
}

// ---------------- per-prior loss terms (override fused in) ----------------
__global__ __launch_bounds__(CBLK) void k_loss(const float*  __restrict__ loc,
                                               const float2* __restrict__ conf,
                                               const float4* __restrict__ priors,
                                               const float*  __restrict__ targets) {
    __shared__ float tx1[OO], ty1[OO], tx2[OO], ty2[OO], tlb[OO];
    __shared__ unsigned s_po[OO];
    __shared__ float swl[8], swc[8];
    __shared__ int   swn[8];
    const int b = blockIdx.y, tid = threadIdx.x;
    const int lane = tid & 31, w = tid >> 5;
    if (tid < OO) {
        const float* t = targets + (size_t)(b * OO + tid) * 5;
        tx1[tid] = t[0]; ty1[tid] = t[1]; tx2[tid] = t[2]; ty2[tid] = t[3]; tlb[tid] = t[4];
        s_po[tid] = 0xFFFFFFFFu - (unsigned)(g_bp_key[b * OO + tid] & 0xFFFFFFFFull);
    }
    __syncthreads();

    const int p = blockIdx.x * CBLK + tid;
    const size_t bp = (size_t)b * PP + p;
    float ov = g_bto[bp];
    int idx = g_bti[bp];
    // fused scatter-override: last-o-wins (ascending o, overwrite)
    #pragma unroll
    for (int o = 0; o < OO; o++)
        if (s_po[o] == (unsigned)p) { ov = 2.0f; idx = o; }

    int cls = (ov < 0.5f) ? 0 : (int)tlb[idx];
    bool pos = cls > 0;

    float4 pr = priors[p];
    float gx = ((tx1[idx] + tx2[idx]) * 0.5f - pr.x) / (0.1f * pr.z);
    float gy = ((ty1[idx] + ty2[idx]) * 0.5f - pr.y) / (0.1f * pr.w);
    float gw = logf((tx2[idx] - tx1[idx]) / pr.z) / 0.2f;
    float gh = logf((ty2[idx] - ty1[idx]) / pr.w) / 0.2f;

    const float* l = loc + bp * 3;
    float q0 = l[0], q1 = l[1], q2 = l[2];
    float d0 = q0 - gx, d1 = q1 - gy, d2 = q2 - gw, d3 = q2 - gh;

    float ad, lloss = 0.0f;
    ad = fabsf(d0); lloss += (ad < 1.0f) ? 0.5f * d0 * d0 : ad - 0.5f;
    ad = fabsf(d1); lloss += (ad < 1.0f) ? 0.5f * d1 * d1 : ad - 0.5f;
    ad = fabsf(d2); lloss += (ad < 1.0f) ? 0.5f * d2 * d2 : ad - 0.5f;
    ad = fabsf(d3); lloss += (ad < 1.0f) ? 0.5f * d3 * d3 : ad - 0.5f;

    float2 c = conf[bp];
    float m = fmaxf(c.x, c.y);
    float lse = m + logf(expf(c.x - m) + expf(c.y - m));
    float picked = cls ? c.y : c.x;
    float ce = lse - picked;

    g_ce[bp] = pos ? 0.0f : fmaxf(ce, 0.0f);

    float rl = pos ? lloss : 0.0f;
    float rc = pos ? ce : 0.0f;
    int   rn = pos ? 1 : 0;
    #pragma unroll
    for (int o = 16; o; o >>= 1) {
        rl += __shfl_down_sync(0xffffffffu, rl, o);
        rc += __shfl_down_sync(0xffffffffu, rc, o);
        rn += __shfl_down_sync(0xffffffffu, rn, o);
    }
    if (lane == 0) { swl[w] = rl; swc[w] = rc; swn[w] = rn; }
    __syncthreads();
    if (tid == 0) {
        float sl = 0.f, sc = 0.f; int sn = 0;
        #pragma unroll
        for (int i = 0; i < 8; i++) { sl += swl[i]; sc += swc[i]; sn += swn[i]; }
        int pb = b * NBLK + blockIdx.x;
        g_pl[pb] = sl; g_pc[pb] = sc; g_pn[pb] = sn;
    }
}

// ---------------- radix pass with parallel suffix scan ----------------
__device__ __forceinline__ int radix_pass(const unsigned* v, unsigned* h0, unsigned* h1,
                                          int n, int sh, unsigned prefmask, unsigned pref,
                                          int tid, int* s_kr, int* s_sel) {
    h0[tid] = 0; h0[tid + 1024] = 0;
    __syncthreads();
    #pragma unroll
    for (int i = 0; i < 32; i++)
        if ((v[i] & prefmask) == pref) atomicAdd(&h0[(v[i] >> sh) & (unsigned)(n - 1)], 1u);
    __syncthreads();
    // inclusive suffix scan (ping-pong Hillis-Steele)
    unsigned* src = h0; unsigned* dst = h1;
    for (int d = 1; d < n; d <<= 1) {
        int i0 = tid, i1 = tid + 1024;
        unsigned a = (i0 < n) ? src[i0] + ((i0 + d < n) ? src[i0 + d] : 0u) : 0u;
        unsigned c = (i1 < n) ? src[i1] + ((i1 + d < n) ? src[i1 + d] : 0u) : 0u;
        if (i0 < n) dst[i0] = a;
        if (i1 < n) dst[i1] = c;
        __syncthreads();
        unsigned* t = src; src = dst; dst = t;
    }
    int kr = *s_kr;
    __syncthreads();
    // largest idx with S[idx] >= kr (unique thread writes)
    #pragma unroll
    for (int j = 0; j < 2; j++) {
        int idx = tid + j * 1024;
        if (idx < n && src[idx] >= (unsigned)kr &&
            (idx == n - 1 || src[idx + 1] < (unsigned)kr)) {
            *s_sel = idx;
            *s_kr = kr - (int)((idx == n - 1) ? 0u : src[idx + 1]);
        }
    }
    __syncthreads();
    return *s_sel;
}

// ---------------- per-batch top-k sum + fused finalize ----------------
__global__ __launch_bounds__(1024) void k_select(float* __restrict__ out) {
    __shared__ unsigned h0[2048], h1[2048];
    __shared__ float sred[1024];
    __shared__ int s_kr, s_k, s_sel;
    __shared__ float s_topk;
    const int b = blockIdx.x, tid = threadIdx.x;

    // load ce_mine (latency-overlapped with partial reduce)
    unsigned v[32];
    #pragma unroll
    for (int i = 0; i < 32; i++)
        v[i] = __float_as_uint(g_ce[(size_t)b * PP + tid + i * 1024]);

    if (tid < 32) {
        float a = 0.f, c = 0.f; int nn = 0;
        #pragma unroll
        for (int j = 0; j < 4; j++) {
            int pb = b * NBLK + tid + 32 * j;
            a += g_pl[pb]; c += g_pc[pb]; nn += g_pn[pb];
        }
        #pragma unroll
        for (int o = 16; o; o >>= 1) {
            a  += __shfl_down_sync(0xffffffffu, a, o);
            c  += __shfl_down_sync(0xffffffffu, c, o);
            nn += __shfl_down_sync(0xffffffffu, nn, o);
        }
        if (tid == 0) {
            g_bl[b] = a; g_bc[b] = c; g_bn[b] = nn;
            int k = 3 * nn; if (k > PP - 1) k = PP - 1;
            s_k = k; s_kr = k;
        }
    }
    __syncthreads();

    if (s_k > 0) {
        unsigned pref = 0, prefmask = 0;
        int sel;
        sel = radix_pass(v, h0, h1, 2048, 21, prefmask, pref, tid, &s_kr, &s_sel);
        pref |= (unsigned)sel << 21; prefmask |= 0x7FFu << 21;
        sel = radix_pass(v, h0, h1, 2048, 10, prefmask, pref, tid, &s_kr, &s_sel);
        pref |= (unsigned)sel << 10; prefmask |= 0x7FFu << 10;
        sel = radix_pass(v, h0, h1, 1024, 0, prefmask, pref, tid, &s_kr, &s_sel);
        pref |= (unsigned)sel;

        const unsigned tbits = pref;
        const int kr = s_kr;
        float acc = 0.0f;
        #pragma unroll
        for (int i = 0; i < 32; i++)
            if (v[i] > tbits) acc += __uint_as_float(v[i]);
        sred[tid] = acc;
        __syncthreads();
        #pragma unroll
        for (int s = 512; s > 0; s >>= 1) {
            if (tid < s) sred[tid] += sred[tid + s];
            __syncthreads();
        }
        if (tid == 0) s_topk = sred[0] + (float)kr * __uint_as_float(tbits);
    } else {
        if (tid == 0) s_topk = 0.0f;
    }
    __syncthreads();

    if (tid == 0) {
        g_bt[b] = s_topk;
        __threadfence();
        int prev = atomicAdd(&g_done, 1);
        if (prev == BB - 1) {
            __threadfence();
            float sl = 0.f, sc = 0.f; int sn = 0;
            for (int b2 = 0; b2 < BB; b2++) {
                sl += g_bl[b2];
                sc += g_bc[b2] + g_bt[b2];
                sn += g_bn[b2];
            }
            float N = (float)sn;
            out[0] = sl / N;
            out[1] = sc / N;
        }
    }
}

extern "C" void kernel_launch(void* const* d_in, const int* in_sizes, int n_in,
                              void* d_out, int out_size) {
    const float*  loc     = (const float*)d_in[0];   // (B, P, 3)
    const float2* conf    = (const float2*)d_in[1];  // (B, P, 2)
    const float4* priors  = (const float4*)d_in[2];  // (P, 4)
    const float*  targets = (const float*)d_in[3];   // (B, O, 5)
    float* out = (float*)d_out;

    k_init<<<1, 1024>>>();
    k_match<<<dim3(NBLK, BB), CBLK>>>(priors, targets);
    k_loss<<<dim3(NBLK, BB), CBLK>>>(loc, conf, priors, targets);
    k_select<<<BB, 1024>>>(out);
}

// round 3
// speedup vs baseline: 3.2258x; 1.7146x over previous
#include <cuda_runtime.h>

#define BB 32
#define PP 32768
#define OO 32
#define CBLK 256
#define NBLK (PP / CBLK)   // 128
#define NBIN 2048

// ---------------- scratch ----------------
__device__ unsigned long long g_bp_key[BB * OO];
__device__ float g_ce[BB * PP];
__device__ int   g_hist[BB * NBIN];
__device__ float g_pl[BB * NBLK], g_pc[BB * NBLK];
__device__ int   g_pn[BB * NBLK];
__device__ float g_cl[BB], g_cc[BB];
__device__ int   g_cn[BB];
__device__ float g_bl[BB], g_bc[BB], g_bt[BB];
__device__ int   g_bn[BB];
__device__ int   g_done;

// ---------------- shared math helpers (must be identical in k_main / k_correct) ----
__device__ __forceinline__ float iou_f(float tx1, float ty1, float tx2, float ty2, float tar,
                                       float px1, float py1, float px2, float py2, float pa) {
    float ww = fmaxf(fminf(tx2, px2) - fmaxf(tx1, px1), 0.0f);
    float hh = fmaxf(fminf(ty2, py2) - fmaxf(ty1, py1), 0.0f);
    float inter = ww * hh;
    return __fdividef(inter, tar + pa - inter);
}

// smooth-L1 + encode + ce for one prior given its matched truth
__device__ __forceinline__ void loss_terms(float ov, float lbl,
                                           float mtx1, float mty1, float mtx2, float mty2,
                                           float prx, float pry, float prz, float prw,
                                           float q0, float q1, float q2,
                                           float cx, float cy,
                                           bool& pos, float& lloss, float& ce, float& cem) {
    int cls = (ov < 0.5f) ? 0 : (int)lbl;
    pos = cls > 0;
    float gx = __fdividef((mtx1 + mtx2) * 0.5f - prx, 0.1f * prz);
    float gy = __fdividef((mty1 + mty2) * 0.5f - pry, 0.1f * prw);
    float gw = __logf(__fdividef(mtx2 - mtx1, prz)) * 5.0f;
    float gh = __logf(__fdividef(mty2 - mty1, prw)) * 5.0f;
    float d0 = q0 - gx, d1 = q1 - gy, d2 = q2 - gw, d3 = q2 - gh;
    float a0 = fabsf(d0), a1 = fabsf(d1), a2 = fabsf(d2), a3 = fabsf(d3);
    float t0 = (a0 < 1.0f) ? 0.5f * d0 * d0 : a0 - 0.5f;
    float t1 = (a1 < 1.0f) ? 0.5f * d1 * d1 : a1 - 0.5f;
    float t2 = (a2 < 1.0f) ? 0.5f * d2 * d2 : a2 - 0.5f;
    float t3 = (a3 < 1.0f) ? 0.5f * d3 * d3 : a3 - 0.5f;
    lloss = (t0 + t1) + (t2 + t3);
    float m = fmaxf(cx, cy);
    float lse = m + __logf(__expf(cx - m) + __expf(cy - m));
    float picked = cls ? cy : cx;
    ce = lse - picked;
    cem = pos ? 0.0f : fmaxf(ce, 0.0f);
}

// ---------------- init ----------------
__global__ void k_init() {
    int i = blockIdx.x * 1024 + threadIdx.x;
    if (i < BB * NBIN) g_hist[i] = 0;
    if (i < BB * OO) g_bp_key[i] = 0x00000000FFFFFFFFull;
    if (i == 0) g_done = 0;
}

// ---------------- fused match + loss ----------------
__global__ __launch_bounds__(CBLK) void k_main(const float*  __restrict__ loc,
                                               const float2* __restrict__ conf,
                                               const float4* __restrict__ priors,
                                               const float*  __restrict__ targets) {
    __shared__ float s_t[6][OO];                 // x1,y1,x2,y2,area,label
    __shared__ unsigned long long sbest[OO];
    __shared__ float s_p[5][CBLK];               // px1,py1,px2,py2,parea
    __shared__ float swl[8], swc[8];
    __shared__ int   swn[8];
    const int b = blockIdx.y, tid = threadIdx.x;
    const int lane = tid & 31, w = tid >> 5;

    if (tid < OO) {
        const float* t = targets + (size_t)(b * OO + tid) * 5;
        float x1 = t[0], y1 = t[1], x2 = t[2], y2 = t[3];
        s_t[0][tid] = x1; s_t[1][tid] = y1; s_t[2][tid] = x2; s_t[3][tid] = y2;
        s_t[4][tid] = (x2 - x1) * (y2 - y1);
        s_t[5][tid] = t[4];
        sbest[tid] = 0ull;
    }
    const int pblk = blockIdx.x * CBLK;
    const int p = pblk + tid;
    float4 pr = priors[p];
    {
        float px1 = pr.x - pr.z * 0.5f, py1 = pr.y - pr.w * 0.5f;
        float px2 = pr.x + pr.z * 0.5f, py2 = pr.y + pr.w * 0.5f;
        s_p[0][tid] = px1; s_p[1][tid] = py1; s_p[2][tid] = px2; s_p[3][tid] = py2;
        s_p[4][tid] = (px2 - px1) * (py2 - py1);
    }
    __syncthreads();

    // lane = truth
    const float Tx1 = s_t[0][lane], Ty1 = s_t[1][lane];
    const float Tx2 = s_t[2][lane], Ty2 = s_t[3][lane];
    const float Tar = s_t[4][lane];

    const int wbase = w * 32;
    unsigned long long rkey = 0ull;
    float my_bto = 0.0f; int my_bti = 0;

    #pragma unroll
    for (int i = 0; i < 32; i++) {
        float bx1 = s_p[0][wbase + i], by1 = s_p[1][wbase + i];
        float bx2 = s_p[2][wbase + i], by2 = s_p[3][wbase + i];
        float ba  = s_p[4][wbase + i];
        float iou = iou_f(Tx1, Ty1, Tx2, Ty2, Tar, bx1, by1, bx2, by2, ba);
        unsigned u = __float_as_uint(iou);
        unsigned m = __reduce_max_sync(0xffffffffu, u);
        unsigned bal = __ballot_sync(0xffffffffu, u == m);
        if (lane == i) { my_bto = __uint_as_float(m); my_bti = __ffs(bal) - 1; }
        unsigned long long key = ((unsigned long long)u << 32) |
                                 (unsigned)(0xFFFFFFFFu - (unsigned)(pblk + wbase + i));
        if (key > rkey) rkey = key;
    }
    atomicMax(&sbest[lane], rkey);

    // ---- loss for my prior (no override; k_correct patches winners) ----
    const size_t bp = (size_t)b * PP + p;
    const int idx = my_bti;
    const float* l = loc + bp * 3;
    float q0 = l[0], q1 = l[1], q2 = l[2];
    float2 c = conf[bp];

    bool pos; float lloss, ce, cem;
    loss_terms(my_bto, s_t[5][idx],
               s_t[0][idx], s_t[1][idx], s_t[2][idx], s_t[3][idx],
               pr.x, pr.y, pr.z, pr.w, q0, q1, q2, c.x, c.y,
               pos, lloss, ce, cem);
    g_ce[bp] = cem;

    // warp-aggregated histogram of ce_mine top-11 bits
    {
        unsigned bin = __float_as_uint(cem) >> 21;
        unsigned mm = __match_any_sync(0xffffffffu, bin);
        if ((mm & ((1u << lane) - 1u)) == 0u)
            atomicAdd(&g_hist[b * NBIN + bin], (int)__popc(mm));
    }

    float rl = pos ? lloss : 0.0f;
    float rc = pos ? ce : 0.0f;
    int   rn = pos ? 1 : 0;
    #pragma unroll
    for (int o = 16; o; o >>= 1) {
        rl += __shfl_down_sync(0xffffffffu, rl, o);
        rc += __shfl_down_sync(0xffffffffu, rc, o);
        rn += __shfl_down_sync(0xffffffffu, rn, o);
    }
    if (lane == 0) { swl[w] = rl; swc[w] = rc; swn[w] = rn; }
    __syncthreads();
    if (tid == 0) {
        float sl = 0.f, sc = 0.f; int sn = 0;
        #pragma unroll
        for (int i = 0; i < 8; i++) { sl += swl[i]; sc += swc[i]; sn += swn[i]; }
        int pb = b * NBLK + blockIdx.x;
        g_pl[pb] = sl; g_pc[pb] = sc; g_pn[pb] = sn;
    }
    if (tid < OO) atomicMax(&g_bp_key[b * OO + tid], sbest[tid]);
}

// ---------------- override correction (one warp per batch) ----------------
__global__ void k_correct(const float*  __restrict__ loc,
                          const float2* __restrict__ conf,
                          const float4* __restrict__ priors,
                          const float*  __restrict__ targets) {
    __shared__ float s_t[6][OO];
    const int b = blockIdx.x, o = threadIdx.x;  // 32 threads
    {
        const float* t = targets + (size_t)(b * OO + o) * 5;
        float x1 = t[0], y1 = t[1], x2 = t[2], y2 = t[3];
        s_t[0][o] = x1; s_t[1][o] = y1; s_t[2][o] = x2; s_t[3][o] = y2;
        s_t[4][o] = (x2 - x1) * (y2 - y1);
        s_t[5][o] = t[4];
    }
    __syncwarp();

    unsigned p = 0xFFFFFFFFu - (unsigned)(g_bp_key[b * OO + o] & 0xFFFFFFFFull);
    // last-o-wins dedup among identical winner priors
    unsigned mm = __match_any_sync(0xffffffffu, p);
    bool active = (31 - __clz(mm)) == o;

    float4 pr = priors[p];
    float px1 = pr.x - pr.z * 0.5f, py1 = pr.y - pr.w * 0.5f;
    float px2 = pr.x + pr.z * 0.5f, py2 = pr.y + pr.w * 0.5f;
    float pa = (px2 - px1) * (py2 - py1);

    // recompute old best_truth (same math/order as k_main: first-index max)
    float obv = 0.0f; int obi = 0;
    #pragma unroll
    for (int o2 = 0; o2 < OO; o2++) {
        float iou = iou_f(s_t[0][o2], s_t[1][o2], s_t[2][o2], s_t[3][o2], s_t[4][o2],
                          px1, py1, px2, py2, pa);
        if (iou > obv) { obv = iou; obi = o2; }
    }

    const size_t bp = (size_t)b * PP + p;
    const float* l = loc + bp * 3;
    float q0 = l[0], q1 = l[1], q2 = l[2];
    float2 c = conf[bp];

    bool pos_o; float ll_o, ce_o, cem_o;
    loss_terms(obv, s_t[5][obi],
               s_t[0][obi], s_t[1][obi], s_t[2][obi], s_t[3][obi],
               pr.x, pr.y, pr.z, pr.w, q0, q1, q2, c.x, c.y,
               pos_o, ll_o, ce_o, cem_o);

    bool pos_n; float ll_n, ce_n, cem_n;
    loss_terms(2.0f, s_t[5][o],
               s_t[0][o], s_t[1][o], s_t[2][o], s_t[3][o],
               pr.x, pr.y, pr.z, pr.w, q0, q1, q2, c.x, c.y,
               pos_n, ll_n, ce_n, cem_n);

    float dl = 0.f, dc = 0.f; int dn = 0;
    if (active) {
        float stored = g_ce[bp];                 // exact bits k_main wrote
        g_ce[bp] = cem_n;
        unsigned ob = __float_as_uint(stored) >> 21;
        unsigned nb = __float_as_uint(cem_n) >> 21;
        if (ob != nb) {
            atomicAdd(&g_hist[b * NBIN + ob], -1);
            atomicAdd(&g_hist[b * NBIN + nb], 1);
        }
        dl = (pos_n ? ll_n : 0.f) - (pos_o ? ll_o : 0.f);
        dc = (pos_n ? ce_n : 0.f) - (pos_o ? ce_o : 0.f);
        dn = (pos_n ? 1 : 0) - (pos_o ? 1 : 0);
    }
    #pragma unroll
    for (int s = 16; s; s >>= 1) {
        dl += __shfl_down_sync(0xffffffffu, dl, s);
        dc += __shfl_down_sync(0xffffffffu, dc, s);
        dn += __shfl_down_sync(0xffffffffu, dn, s);
    }
    if (o == 0) { g_cl[b] = dl; g_cc[b] = dc; g_cn[b] = dn; }
}

// ---------------- scan helpers ----------------
__device__ unsigned* suffix_scan(unsigned* h0, unsigned* h1, int n, int tid) {
    unsigned* src = h0; unsigned* dst = h1;
    for (int d = 1; d < n; d <<= 1) {
        int i0 = tid, i1 = tid + 1024;
        unsigned a = (i0 < n) ? src[i0] + ((i0 + d < n) ? src[i0 + d] : 0u) : 0u;
        unsigned c2 = (i1 < n) ? src[i1] + ((i1 + d < n) ? src[i1 + d] : 0u) : 0u;
        __syncthreads();
        if (i0 < n) dst[i0] = a;
        if (i1 < n) dst[i1] = c2;
        __syncthreads();
        unsigned* t = src; src = dst; dst = t;
    }
    return src;
}

__device__ int pick_bucket(unsigned* S, int n, int tid, int* s_kr, int* s_sel) {
    int kr = *s_kr;
    __syncthreads();
    #pragma unroll
    for (int j = 0; j < 2; j++) {
        int idx = tid + j * 1024;
        if (idx < n && S[idx] >= (unsigned)kr &&
            (idx == n - 1 || S[idx + 1] < (unsigned)kr)) {
            *s_sel = idx;
            *s_kr = kr - (int)((idx == n - 1) ? 0u : S[idx + 1]);
        }
    }
    __syncthreads();
    return *s_sel;
}

// ---------------- per-batch top-k + finalize ----------------
__global__ __launch_bounds__(1024) void k_select(float* __restrict__ out) {
    __shared__ unsigned h0[2048], h1[2048];
    __shared__ float sw32[32];
    __shared__ int s_kr, s_k, s_sel;
    __shared__ float s_topk;
    const int b = blockIdx.x, tid = threadIdx.x;
    const int lane = tid & 31;

    unsigned v[32];
    #pragma unroll
    for (int i = 0; i < 32; i++)
        v[i] = __float_as_uint(g_ce[(size_t)b * PP + tid + i * 1024]);

    // pass-1 histogram comes precomputed
    h0[tid] = (unsigned)g_hist[b * NBIN + tid];
    h0[tid + 1024] = (unsigned)g_hist[b * NBIN + tid + 1024];

    if (tid < 32) {
        float a = 0.f, c = 0.f; int nn = 0;
        #pragma unroll
        for (int j = 0; j < 4; j++) {
            int pb = b * NBLK + tid + 32 * j;
            a += g_pl[pb]; c += g_pc[pb]; nn += g_pn[pb];
        }
        #pragma unroll
        for (int o = 16; o; o >>= 1) {
            a  += __shfl_down_sync(0xffffffffu, a, o);
            c  += __shfl_down_sync(0xffffffffu, c, o);
            nn += __shfl_down_sync(0xffffffffu, nn, o);
        }
        if (tid == 0) {
            a += g_cl[b]; c += g_cc[b]; nn += g_cn[b];
            g_bl[b] = a; g_bc[b] = c; g_bn[b] = nn;
            int k = 3 * nn; if (k > PP - 1) k = PP - 1;
            s_k = k; s_kr = k;
        }
    }
    __syncthreads();

    if (s_k > 0) {
        // pass 1: bits [31:21]
        unsigned* S = suffix_scan(h0, h1, 2048, tid);
        int sel = pick_bucket(S, 2048, tid, &s_kr, &s_sel);
        unsigned pref = (unsigned)sel << 21, prefmask = 0x7FFu << 21;

        // pass 2: bits [20:10]
        h0[tid] = 0; h0[tid + 1024] = 0;
        __syncthreads();
        #pragma unroll
        for (int i = 0; i < 32; i++) {
            bool hit = (v[i] & prefmask) == pref;
            unsigned act = __ballot_sync(0xffffffffu, hit);
            if (hit) {
                unsigned bin = (v[i] >> 10) & 0x7FFu;
                unsigned mm = __match_any_sync(act, bin);
                if ((mm & ((1u << lane) - 1u)) == 0u)
                    atomicAdd(&h0[bin], __popc(mm));
            }
        }
        __syncthreads();
        S = suffix_scan(h0, h1, 2048, tid);
        sel = pick_bucket(S, 2048, tid, &s_kr, &s_sel);
        pref |= (unsigned)sel << 10; prefmask |= 0x7FFu << 10;

        // pass 3: bits [9:0]
        h0[tid] = 0; h0[tid + 1024] = 0;
        __syncthreads();
        #pragma unroll
        for (int i = 0; i < 32; i++) {
            bool hit = (v[i] & prefmask) == pref;
            unsigned act = __ballot_sync(0xffffffffu, hit);
            if (hit) {
                unsigned bin = v[i] & 0x3FFu;
                unsigned mm = __match_any_sync(act, bin);
                if ((mm & ((1u << lane) - 1u)) == 0u)
                    atomicAdd(&h0[bin], __popc(mm));
            }
        }
        __syncthreads();
        S = suffix_scan(h0, h1, 1024, tid);
        sel = pick_bucket(S, 1024, tid, &s_kr, &s_sel);
        pref |= (unsigned)sel;

        const unsigned tbits = pref;
        const int kr = s_kr;
        float acc = 0.0f;
        #pragma unroll
        for (int i = 0; i < 32; i++)
            if (v[i] > tbits) acc += __uint_as_float(v[i]);
        #pragma unroll
        for (int o = 16; o; o >>= 1) acc += __shfl_down_sync(0xffffffffu, acc, o);
        if (lane == 0) sw32[tid >> 5] = acc;
        __syncthreads();
        if (tid < 32) {
            float x = sw32[tid];
            #pragma unroll
            for (int o = 16; o; o >>= 1) x += __shfl_down_sync(0xffffffffu, x, o);
            if (tid == 0) s_topk = x + (float)kr * __uint_as_float(tbits);
        }
    } else {
        if (tid == 0) s_topk = 0.0f;
    }
    __syncthreads();

    if (tid == 0) {
        g_bt[b] = s_topk;
        __threadfence();
        int prev = atomicAdd(&g_done, 1);
        if (prev == BB - 1) {
            __threadfence();
            float sl = 0.f, sc = 0.f; int sn = 0;
            for (int b2 = 0; b2 < BB; b2++) {
                sl += g_bl[b2];
                sc += g_bc[b2] + g_bt[b2];
                sn += g_bn[b2];
            }
            float N = (float)sn;
            out[0] = sl / N;
            out[1] = sc / N;
        }
    }
}

extern "C" void kernel_launch(void* const* d_in, const int* in_sizes, int n_in,
                              void* d_out, int out_size) {
    const float*  loc     = (const float*)d_in[0];   // (B, P, 3)
    const float2* conf    = (const float2*)d_in[1];  // (B, P, 2)
    const float4* priors  = (const float4*)d_in[2];  // (P, 4)
    const float*  targets = (const float*)d_in[3];   // (B, O, 5)
    float* out = (float*)d_out;

    k_init<<<64, 1024>>>();
    k_main<<<dim3(NBLK, BB), CBLK>>>(loc, conf, priors, targets);
    k_correct<<<BB, 32>>>(loc, conf, priors, targets);
    k_select<<<BB, 1024>>>(out);
}